// round 17
// baseline (speedup 1.0000x reference)
#include <cuda_runtime.h>
#include <cuda_fp16.h>
#include <cstdint>
#include <cstddef>

// ---------------------------------------------------------------------------
// 20 independent GEMMs (block-diagonal ensemble linear)
//   x:[32768,4000] f32, W:[2000,4000] f32, out:[32768,2000] f32
//   block n: out[:,n*100:+100] = x[:,n*200:+200] @ W[n*100:+100, n*200:+200]^T
//
// R17 = R16 (227.5us) + A-path restructure:
//   * per-chunk convert pass: f32 A chunk (cp.async staging) -> fp16 A buffer
//     (each element converted ONCE, vs twice in the old per-fragment path).
//     Thread (r = tid/2, h = tid&1) does 7x LDS.128 + 14 CVT + 7 STS.64;
//     bank-audited conflict-free at stride 56.
//   * A fragments via ldmatrix.m8n8.x4 on the fp16 buffer (1 instr / m16
//     tile / k16 step, stride 112B conflict-free), B via ldmatrix.x2 (R16).
//   * SMEM: B 48KB + 2x56KB f32 staging ring + 28KB fp16 A = 191.7KB.
// Core: fp16 m16n8k16 HMMA (fp32 accum), 512 thr, 148 persistent CTAs over
// 2560 units, KCH=4 (48,48,48,56), W resident fp16.
// ---------------------------------------------------------------------------

static constexpr int NUM     = 20;
static constexpr int IN_SZ   = 200;
static constexpr int OUT_SZ  = 100;
static constexpr int X_LD    = 4000;
static constexpr int W_LD    = 4000;
static constexpr int OUT_LD  = 2000;

static constexpr int M_TILE  = 256;
static constexpr int KCH     = 4;                 // 48,48,48,56
static constexpr int MT_PER_N = 128;              // 32768/256
static constexpr int UNITS   = NUM * MT_PER_N;    // 2560 work units
static constexpr int NCTAS   = 148;               // one per SM

static constexpr int N_TILE  = 112;               // 14 n8 tiles, 7/7 balanced
static constexpr int STR_S   = 56;                // f32 staging row stride
static constexpr int STR_F   = 56;                // fp16 A row stride (halves)
static constexpr int STR_BH  = 216;               // B row stride (halves)

static constexpr int S_ELEMS = M_TILE * STR_S;            // 14336 f32 / slot
static constexpr int B_BYTES = N_TILE * STR_BH * 2;       // 48384
static constexpr int OFF_S   = B_BYTES;
static constexpr int OFF_F   = B_BYTES + 2 * S_ELEMS * 4; // 163072
static constexpr int F_BYTES = M_TILE * STR_F * 2;        // 28672
static constexpr int SMEM_BYTES = OFF_F + F_BYTES;        // 191744

static constexpr int THREADS = 512;               // 16 warps: 8(wm) x 2(wn)
// warp tile 32(M) x 56(N): 2 m16 x 7 n8

// ---------------------------------------------------------------------------
__device__ __forceinline__ uint32_t smem_u32(const void* p) {
    uint32_t a;
    asm("{ .reg .u64 t; cvta.to.shared.u64 t, %1; cvt.u32.u64 %0, t; }"
        : "=r"(a) : "l"(p));
    return a;
}
__device__ __forceinline__ void cp16(uint32_t dst, const float* src) {
    asm volatile("cp.async.cg.shared.global [%0], [%1], 16;"
                 :: "r"(dst), "l"(src));
}
#define CP_COMMIT() asm volatile("cp.async.commit_group;" ::: "memory")
#define CP_WAIT(n)  asm volatile("cp.async.wait_group %0;" :: "n"(n) : "memory")

// pack two f32 -> f16x2 reg; lo half = first (lower-k) element
__device__ __forceinline__ uint32_t cvt_f16x2(float lo, float hi) {
    uint32_t r;
    asm("cvt.rn.f16x2.f32 %0, %1, %2;" : "=r"(r) : "f"(hi), "f"(lo));
    return r;
}

__device__ __forceinline__ void ldsm_x2(uint32_t& r0, uint32_t& r1, uint32_t addr) {
    asm volatile("ldmatrix.sync.aligned.m8n8.x2.shared.b16 {%0,%1}, [%2];"
                 : "=r"(r0), "=r"(r1) : "r"(addr));
}
__device__ __forceinline__ void ldsm_x4(uint32_t& r0, uint32_t& r1,
                                        uint32_t& r2, uint32_t& r3, uint32_t addr) {
    asm volatile("ldmatrix.sync.aligned.m8n8.x4.shared.b16 {%0,%1,%2,%3}, [%4];"
                 : "=r"(r0), "=r"(r1), "=r"(r2), "=r"(r3) : "r"(addr));
}

// D(16x8,f32) += A(16x16,f16) * B(16x8,f16)  [row.col]
__device__ __forceinline__ void mma_f16_k16(float c[4],
                                            uint32_t a0, uint32_t a1, uint32_t a2, uint32_t a3,
                                            uint32_t b0, uint32_t b1) {
    asm volatile(
        "mma.sync.aligned.m16n8k16.row.col.f32.f16.f16.f32 "
        "{%0,%1,%2,%3}, {%4,%5,%6,%7}, {%8,%9}, {%0,%1,%2,%3};"
        : "+f"(c[0]), "+f"(c[1]), "+f"(c[2]), "+f"(c[3])
        : "r"(a0), "r"(a1), "r"(a2), "r"(a3), "r"(b0), "r"(b1));
}
// D(16x8,f32) += A(16x8,f16) * B(8x8,f16)  [row.col]
__device__ __forceinline__ void mma_f16_k8(float c[4],
                                           uint32_t a0, uint32_t a1, uint32_t b0) {
    asm volatile(
        "mma.sync.aligned.m16n8k8.row.col.f32.f16.f16.f32 "
        "{%0,%1,%2,%3}, {%4,%5}, {%6}, {%0,%1,%2,%3};"
        : "+f"(c[0]), "+f"(c[1]), "+f"(c[2]), "+f"(c[3])
        : "r"(a0), "r"(a1), "r"(b0));
}

// ---------------------------------------------------------------------------
// Persistent CTA over flattened (n, M-tile) units u = n*128 + mt.
// ---------------------------------------------------------------------------
__global__ void __launch_bounds__(THREADS, 1)
ensemble_linear_f16c_kernel(const float* __restrict__ x,
                            const float* __restrict__ W,
                            float* __restrict__ out) {
    extern __shared__ char smem[];
    __half* Bh  = (__half*)smem;                    // [112][216] fp16
    float*  Srn = (float*)(smem + OFF_S);           // [2][256*56] f32 staging
    const uint32_t s_base = smem_u32(Srn);
    const uint32_t b_base = smem_u32(Bh);
    const uint32_t f_base = b_base + OFF_F;         // fp16 A buffer [256][56]

    const int tid = threadIdx.x;
    const int wid = tid >> 5;
    const int lid = tid & 31;
    const int g   = lid >> 2;    // 0..7
    const int tg  = lid & 3;     // 0..3
    const int wm  = wid >> 1;    // 0..7 (M)
    const int wn  = wid & 1;     // 0..1 (N)

    // ldmatrix lane address components (constant over mainloop)
    // B (x2): row = wn*56 + (lid&7) + matrix-half k offset 8 halves
    const uint32_t b_lane_off =
        (uint32_t)(((wn * 56 + (lid & 7)) * STR_BH + ((lid >> 3) & 1) * 8) * 2);
    // A (x4): row = wm*32 + (lid&7) + ((lid>>3)&1)*8, k half-offset (lid>>4)*8
    const int a_row = wm * 32 + (lid & 7) + ((lid >> 3) & 1) * 8;
    const uint32_t a_lane_off =
        (uint32_t)((a_row * STR_F + (lid >> 4) * 8) * 2);
    // A tail (x2, lanes 0..15 used): row only
    const uint32_t at_lane_off = (uint32_t)((a_row * STR_F + 48) * 2);

    const int cta    = blockIdx.x;
    const int ustart = (cta * UNITS) / NCTAS;
    const int uend   = ((cta + 1) * UNITS) / NCTAS;
    const int total_chunks = (uend - ustart) * KCH;

    // ---- W staging (rows 0..99 -> fp16, rows 100..111 zero) ----------------
    auto stage_W = [&](int nn) {
        const float* wbase = W + (size_t)nn * OUT_SZ * W_LD + (size_t)nn * IN_SZ;
        for (int idx = tid; idx < OUT_SZ * 50; idx += THREADS) {
            int r  = idx / 50;
            int c4 = idx - r * 50;
            float4 v = *(const float4*)(wbase + (size_t)r * W_LD + c4 * 4);
            uint2 u;
            u.x = cvt_f16x2(v.x, v.y);
            u.y = cvt_f16x2(v.z, v.w);
            *(uint2*)(Bh + r * STR_BH + c4 * 4) = u;
        }
        for (int i = tid; i < 12 * STR_BH; i += THREADS) {
            int r = 100 + i / STR_BH;
            int cc = i - (i / STR_BH) * STR_BH;
            Bh[r * STR_BH + cc] = __float2half(0.0f);
        }
    };

    // ---- A chunk producer (cp.async). kc<3: 48 cols; kc==3: 56 cols --------
    auto produce = [&](int c) {
        if (c < total_chunks) {
            const int u  = ustart + (c >> 2);
            const int kc = c & 3;
            const int np = u >> 7;       // u / 128
            const int mt = u & 127;
            const float* xs = x + (size_t)np * IN_SZ
                                + (size_t)mt * M_TILE * X_LD + kc * 48;
            uint32_t dst = s_base + (uint32_t)((c & 1) * S_ELEMS) * 4u;
            if (kc < 3) {
                // 256 rows x 12 float4 = 3072 ops -> 6/thread
                #pragma unroll
                for (int j = 0; j < 6; ++j) {
                    int idx = tid + j * THREADS;
                    int r = idx / 12;
                    int i = idx - r * 12;
                    cp16(dst + (uint32_t)(r * STR_S + i * 4) * 4u,
                         xs + (size_t)r * X_LD + i * 4);
                }
            } else {
                // 256 rows x 14 float4 = 3584 ops -> 7/thread
                #pragma unroll
                for (int j = 0; j < 7; ++j) {
                    int idx = tid + j * THREADS;
                    int r = idx / 14;
                    int i = idx - r * 14;
                    cp16(dst + (uint32_t)(r * STR_S + i * 4) * 4u,
                         xs + (size_t)r * X_LD + i * 4);
                }
            }
        }
        CP_COMMIT();
    };

    float acc[2][7][4];
    #pragma unroll
    for (int t = 0; t < 2; ++t)
        #pragma unroll
        for (int j = 0; j < 7; ++j)
            #pragma unroll
            for (int q = 0; q < 4; ++q) acc[t][j][q] = 0.0f;

    int cur_n = ustart >> 7;
    stage_W(cur_n);                 // visibility: first loop-top __syncthreads

    produce(0);
    produce(1);

    // convert-pass thread mapping (constant)
    const int cv_r = tid >> 1;      // 0..255
    const int cv_h = tid & 1;       // 0/1 -> cols 0..27 / 28..55

    // ---- mainloop ----------------------------------------------------------
    for (int c = 0; c < total_chunks; ++c) {
        CP_WAIT(1);            // chunk c f32 staged (chunk c+1 may be in flight)
        __syncthreads();       // staging visible; F free (prior compute done)

        const int u  = ustart + (c >> 2);
        const int kc = c & 3;
        const int n  = u >> 7;
        const int mt = u & 127;

        if (n != cur_n) {      // block switch (<=1 per CTA); only at kc==0
            stage_W(n);        // visible after the convert barrier below
            cur_n = n;
        }

        // ---- convert chunk c: f32 staging -> fp16 A buffer (56 cols) -------
        {
            const float* src = Srn + (c & 1) * S_ELEMS + cv_r * STR_S + cv_h * 28;
            const uint32_t dst = f_base + (uint32_t)((cv_r * STR_F + cv_h * 28) * 2);
            #pragma unroll
            for (int i = 0; i < 7; ++i) {
                float4 v = *(const float4*)(src + 4 * i);
                uint32_t p0 = cvt_f16x2(v.x, v.y);
                uint32_t p1 = cvt_f16x2(v.z, v.w);
                asm volatile("st.shared.v2.b32 [%0], {%1, %2};"
                             :: "r"(dst + 8u * i), "r"(p0), "r"(p1) : "memory");
            }
        }
        __syncthreads();       // fp16 A (and any W staging) visible

        produce(c + 2);        // refills staging slot (c&1) — safe after sync

        #pragma unroll
        for (int ks = 0; ks < 3; ++ks) {      // 3 k16 steps (all chunks)
            const int k0 = ks * 16;
            uint32_t a[2][4];
            #pragma unroll
            for (int t = 0; t < 2; ++t)
                ldsm_x4(a[t][0], a[t][1], a[t][2], a[t][3],
                        f_base + a_lane_off
                               + (uint32_t)((t * 16 * STR_F + k0) * 2));
            uint32_t b[7][2];
            #pragma unroll
            for (int j = 0; j < 7; ++j)
                ldsm_x2(b[j][0], b[j][1],
                        b_base + b_lane_off
                               + (uint32_t)((j * 8 * STR_BH + kc * 48 + k0) * 2));
            #pragma unroll
            for (int t = 0; t < 2; ++t)
                #pragma unroll
                for (int j = 0; j < 7; ++j)
                    mma_f16_k16(acc[t][j], a[t][0], a[t][1], a[t][2], a[t][3],
                                b[j][0], b[j][1]);
        }

        if (kc == 3) {
            // extra k8 step: k = 192..199 (chunk-local cols 48..55)
            uint32_t a[2][2];
            #pragma unroll
            for (int t = 0; t < 2; ++t)
                ldsm_x2(a[t][0], a[t][1],
                        f_base + at_lane_off + (uint32_t)(t * 16 * STR_F * 2));
            uint32_t b[7];
            #pragma unroll
            for (int j = 0; j < 7; ++j) {
                const int col = wn * 56 + j * 8 + g;
                b[j] = *(const uint32_t*)(Bh + col * STR_BH + 192 + 2 * tg);
            }
            #pragma unroll
            for (int t = 0; t < 2; ++t)
                #pragma unroll
                for (int j = 0; j < 7; ++j)
                    mma_f16_k8(acc[t][j], a[t][0], a[t][1], b[j]);
        }

        // ---- per-M-tile epilogue after last k-chunk ------------------------
        if (kc == KCH - 1) {
            const int row_base = mt * M_TILE + wm * 32;
            #pragma unroll
            for (int t = 0; t < 2; ++t) {
                const int r0 = row_base + t * 16 + g;
                float* orow = out + (size_t)r0 * OUT_LD + (size_t)n * OUT_SZ;
                #pragma unroll
                for (int j = 0; j < 7; ++j) {
                    const int cgl = wn * 56 + j * 8 + 2 * tg;   // even, 0..110
                    if (cgl < OUT_SZ) {
                        *(float2*)(orow + cgl) =
                            make_float2(acc[t][j][0], acc[t][j][1]);
                        *(float2*)(orow + (size_t)8 * OUT_LD + cgl) =
                            make_float2(acc[t][j][2], acc[t][j][3]);
                    }
                    #pragma unroll
                    for (int q = 0; q < 4; ++q) acc[t][j][q] = 0.0f;
                }
            }
        }
    }
}

// ---------------------------------------------------------------------------
extern "C" void kernel_launch(void* const* d_in, const int* in_sizes, int n_in,
                              void* d_out, int out_size) {
    const float* x = (const float*)d_in[0];   // [32768, 4000]
    const float* W = (const float*)d_in[1];   // [2000, 4000]
    float* out = (float*)d_out;               // [32768, 2000]

    static bool attr_set = false;
    if (!attr_set) {
        cudaFuncSetAttribute(ensemble_linear_f16c_kernel,
                             cudaFuncAttributeMaxDynamicSharedMemorySize,
                             SMEM_BYTES);
        attr_set = true;
    }

    ensemble_linear_f16c_kernel<<<NCTAS, THREADS, SMEM_BYTES>>>(x, W, out);
}